// round 8
// baseline (speedup 1.0000x reference)
#include <cuda_runtime.h>
#include <cstdint>

// 2-layer LSTM (HID=10), B=2048, T=1024, future=64.
// R7 (= R5 retried; prior failure was a container/context error, not the kernel):
// layer-pipelined across 2 warps per CTA.
//   warp 0 (A): layer 1 for 3 batch elements, all timesteps
//   warp 1 (B): layer 2 + y for the same elements, one step behind
// h1 handed A->B via double-buffered smem, ONE __syncthreads per step.
// Future phase (x = y_prev breaks the lag) runs serial with 2 barriers/step.
// tanh.approx nonlinearities (sigmoid = 0.5*tanh(z/2)+0.5, 0.5 pre-folded),
// packed f32x2 FMAs, tree-reduced dots.

#define HID 10

typedef unsigned long long u64;

__device__ __forceinline__ u64 pk(float a, float b) {
    u64 r; asm("mov.b64 %0, {%1, %2};" : "=l"(r) : "f"(a), "f"(b)); return r;
}
__device__ __forceinline__ float2 upk(u64 v) {
    float2 f; asm("mov.b64 {%0, %1}, %2;" : "=f"(f.x), "=f"(f.y) : "l"(v)); return f;
}
__device__ __forceinline__ u64 ffma2(u64 a, u64 b, u64 c) {
    u64 d; asm("fma.rn.f32x2 %0, %1, %2, %3;" : "=l"(d) : "l"(a), "l"(b), "l"(c)); return d;
}
__device__ __forceinline__ u64 fmul2(u64 a, u64 b) {
    u64 d; asm("mul.rn.f32x2 %0, %1, %2;" : "=l"(d) : "l"(a), "l"(b)); return d;
}
__device__ __forceinline__ u64 fadd2(u64 a, u64 b) {
    u64 d; asm("add.rn.f32x2 %0, %1, %2;" : "=l"(d) : "l"(a), "l"(b)); return d;
}
__device__ __forceinline__ float hsum(u64 v) { float2 f = upk(v); return f.x + f.y; }

__device__ __forceinline__ float tanh_fast(float z) {
    float r; asm("tanh.approx.f32 %0, %1;" : "=f"(r) : "f"(z)); return r;
}
// A is already z/2 : sigmoid(z) = 0.5*tanh(z/2) + 0.5
__device__ __forceinline__ float sig_half(float A) {
    return fmaf(tanh_fast(A), 0.5f, 0.5f);
}

// dot of 5 packed pairs + packed bias, tree-reduced
__device__ __forceinline__ u64 dot5(const u64* h, const u64 w[5], u64 biasp) {
    u64 a = ffma2(h[0], w[0], biasp);
    u64 b = fmul2(h[1], w[1]);
    a = ffma2(h[2], w[2], a);
    b = ffma2(h[3], w[3], b);
    a = ffma2(h[4], w[4], a);
    return fadd2(a, b);
}

__global__ void __launch_bounds__(64, 4)
lstm2_pipe_kernel(const float* __restrict__ x,
                  const float* __restrict__ Wih1, const float* __restrict__ Whh1,
                  const float* __restrict__ bih1, const float* __restrict__ bhh1,
                  const float* __restrict__ Wih2, const float* __restrict__ Whh2,
                  const float* __restrict__ bih2, const float* __restrict__ bhh2,
                  const float* __restrict__ Wlin, const float* __restrict__ blin,
                  float* __restrict__ out,
                  int B, int T, int TT)
{
    const int tid  = threadIdx.x;
    const int wrp  = tid >> 5;          // 0 = layer1 warp (A), 1 = layer2 warp (B)
    const int lane = tid & 31;
    int e = lane / HID;
    int u = lane - e * HID;
    const bool lane_ok = (e < 3);
    const int ec = lane_ok ? e : 2;
    const int g0 = ec * HID;
    const int b = blockIdx.x * 3 + ec;
    const bool wr = lane_ok && (b < B) && (u == 0);   // used by warp B
    const int bc = (b < B) ? b : (B - 1);

    const float scl[4] = {0.5f, 0.5f, 1.0f, 0.5f};   // i,f,o sigmoid-via-tanh; g plain

    __shared__ float4 h1buf[2][3][3];   // double-buffered h1 (12 floats/elem)
    __shared__ float  ybuf[3];          // y handoff for future phase

    const unsigned FULL = 0xffffffffu;

    // ---------------- per-warp persistent state ----------------
    u64 Whh1r[4][5]; float wx1[4], bias1[4];
    u64 h1pA[5]; float c1 = 0.0f;
    u64 Whh2r[4][5], Wih2r[4][5], WL[5]; u64 b2p[4]; float bl = 0.0f;
    u64 h2p[5]; float c2 = 0.0f;

#pragma unroll
    for (int p = 0; p < 5; ++p) { h1pA[p] = 0ull; h2p[p] = 0ull; }

    if (wrp == 0) {
#pragma unroll
        for (int g = 0; g < 4; ++g) {
            const float s = scl[g];
            const int r = g * HID + u;
            bias1[g] = (__ldg(&bih1[r]) + __ldg(&bhh1[r])) * s;
            wx1[g]   = __ldg(&Wih1[r]) * s;
#pragma unroll
            for (int p = 0; p < 5; ++p) {
                float2 w = *(const float2*)&Whh1[r * HID + 2 * p];
                Whh1r[g][p] = pk(w.x * s, w.y * s);
            }
        }
    } else {
#pragma unroll
        for (int g = 0; g < 4; ++g) {
            const float s = scl[g];
            const int r = g * HID + u;
            b2p[g] = pk((__ldg(&bih2[r]) + __ldg(&bhh2[r])) * s, 0.0f);
#pragma unroll
            for (int p = 0; p < 5; ++p) {
                float2 w;
                w = *(const float2*)&Wih2[r * HID + 2 * p]; Wih2r[g][p] = pk(w.x * s, w.y * s);
                w = *(const float2*)&Whh2[r * HID + 2 * p]; Whh2r[g][p] = pk(w.x * s, w.y * s);
            }
        }
#pragma unroll
        for (int p = 0; p < 5; ++p) {
            float2 w = *(const float2*)&Wlin[2 * p];
            WL[p] = pk(w.x, w.y);
        }
        bl = __ldg(&blin[0]);
    }

    // ---- warp A: one layer-1 step (gates -> h1 -> STS + self-bcast) ----
    auto stepA = [&](float xt, int slot) {
        float gt[4];
#pragma unroll
        for (int g = 0; g < 4; ++g) {
            u64 biasx = pk(fmaf(wx1[g], xt, bias1[g]), 0.0f);
            gt[g] = hsum(dot5(h1pA, Whh1r[g], biasx));
        }
        const float si = sig_half(gt[0]);
        const float sf = sig_half(gt[1]);
        const float tg = tanh_fast(gt[2]);
        const float so = sig_half(gt[3]);
        c1 = fmaf(sf, c1, si * tg);
        const float h1u = so * tanh_fast(c1);
        if (lane_ok) ((float*)&h1buf[slot][ec][0])[u] = h1u;
        float v0 = __shfl_sync(FULL, h1u, g0 + 0);
        float v1 = __shfl_sync(FULL, h1u, g0 + 1);
        float v2 = __shfl_sync(FULL, h1u, g0 + 2);
        float v3 = __shfl_sync(FULL, h1u, g0 + 3);
        float v4 = __shfl_sync(FULL, h1u, g0 + 4);
        float v5 = __shfl_sync(FULL, h1u, g0 + 5);
        float v6 = __shfl_sync(FULL, h1u, g0 + 6);
        float v7 = __shfl_sync(FULL, h1u, g0 + 7);
        float v8 = __shfl_sync(FULL, h1u, g0 + 8);
        float v9 = __shfl_sync(FULL, h1u, g0 + 9);
        h1pA[0] = pk(v0, v1); h1pA[1] = pk(v2, v3); h1pA[2] = pk(v4, v5);
        h1pA[3] = pk(v6, v7); h1pA[4] = pk(v8, v9);
    };

    // ---- warp B: one layer-2 + y step; reads h1 from smem slot; returns y ----
    auto stepB = [&](int slot) -> float {
        u64 hh[5];
        {
            float4 A0 = h1buf[slot][ec][0];
            float4 A1 = h1buf[slot][ec][1];
            float4 A2 = h1buf[slot][ec][2];
            hh[0] = pk(A0.x, A0.y); hh[1] = pk(A0.z, A0.w);
            hh[2] = pk(A1.x, A1.y); hh[3] = pk(A1.z, A1.w);
            hh[4] = pk(A2.x, A2.y);
        }
        float gt[4];
#pragma unroll
        for (int g = 0; g < 4; ++g) {
            u64 a = dot5(hh, Wih2r[g], b2p[g]);     // smem-dependent half first
            u64 c = dot5(h2p, Whh2r[g], a);
            gt[g] = hsum(c);
        }
        const float si = sig_half(gt[0]);
        const float sf = sig_half(gt[1]);
        const float tg = tanh_fast(gt[2]);
        const float so = sig_half(gt[3]);
        c2 = fmaf(sf, c2, si * tg);
        const float h2u = so * tanh_fast(c2);
        float v0 = __shfl_sync(FULL, h2u, g0 + 0);
        float v1 = __shfl_sync(FULL, h2u, g0 + 1);
        float v2 = __shfl_sync(FULL, h2u, g0 + 2);
        float v3 = __shfl_sync(FULL, h2u, g0 + 3);
        float v4 = __shfl_sync(FULL, h2u, g0 + 4);
        float v5 = __shfl_sync(FULL, h2u, g0 + 5);
        float v6 = __shfl_sync(FULL, h2u, g0 + 6);
        float v7 = __shfl_sync(FULL, h2u, g0 + 7);
        float v8 = __shfl_sync(FULL, h2u, g0 + 8);
        float v9 = __shfl_sync(FULL, h2u, g0 + 9);
        h2p[0] = pk(v0, v1); h2p[1] = pk(v2, v3); h2p[2] = pk(v4, v5);
        h2p[3] = pk(v6, v7); h2p[4] = pk(v8, v9);
        u64 ya = ffma2(h2p[0], WL[0], pk(bl, 0.0f));
        u64 yb = fmul2(h2p[1], WL[1]);
        ya = ffma2(h2p[2], WL[2], ya);
        yb = ffma2(h2p[3], WL[3], yb);
        ya = ffma2(h2p[4], WL[4], ya);
        return hsum(fadd2(ya, yb));
    };

    const float* xrow = x + (size_t)bc * T;
    float* orow = out + (size_t)bc * TT;

    // =======================================================================
    // Pipelined phase: iteration i — A does L1(i), B does L2(i-1)+y(i-1).
    // One __syncthreads per step. h1buf double-buffered on i&1.
    // =======================================================================
    const bool fast4 = ((((uintptr_t)xrow) & 15u) == 0) && ((T & 3) == 0) && (T > 0);
    if (fast4) {
        const float4* xq = (const float4*)xrow;
        const int nc = T >> 2;
        float4 xv = make_float4(0.f, 0.f, 0.f, 0.f);
        if (wrp == 0) xv = __ldg(&xq[0]);
        for (int ci = 0; ci < nc; ++ci) {
            const int i0 = ci << 2;
            float4 xn = make_float4(0.f, 0.f, 0.f, 0.f);
            if (wrp == 0 && ci + 1 < nc) xn = __ldg(&xq[ci + 1]);

            if (wrp == 0) stepA(xv.x, (i0 + 0) & 1);
            else if (i0 > 0) { float y = stepB((i0 - 1) & 1); if (wr) orow[i0 - 1] = y; }
            __syncthreads();
            if (wrp == 0) stepA(xv.y, (i0 + 1) & 1);
            else { float y = stepB(i0 & 1); if (wr) orow[i0] = y; }
            __syncthreads();
            if (wrp == 0) stepA(xv.z, (i0 + 2) & 1);
            else { float y = stepB((i0 + 1) & 1); if (wr) orow[i0 + 1] = y; }
            __syncthreads();
            if (wrp == 0) stepA(xv.w, (i0 + 3) & 1);
            else { float y = stepB((i0 + 2) & 1); if (wr) orow[i0 + 2] = y; }
            __syncthreads();

            xv = xn;
        }
    } else {
        for (int i = 0; i < T; ++i) {
            if (wrp == 0) stepA(__ldg(&xrow[i]), i & 1);
            else if (i > 0) { float y = stepB((i - 1) & 1); if (wr) orow[i - 1] = y; }
            __syncthreads();
        }
    }

    // =======================================================================
    // Drain + future phase (serial: y(t-1) feeds x(t)). Two barriers/step.
    // =======================================================================
    for (int t = T; ; ++t) {
        if (wrp == 1) {
            float y = stepB((t - 1) & 1);
            if (wr) orow[t - 1] = y;
            if (lane_ok && u == 0) ybuf[ec] = y;
        }
        __syncthreads();
        if (t == TT) break;
        if (wrp == 0) {
            stepA(ybuf[ec], t & 1);
        }
        __syncthreads();
    }
}

extern "C" void kernel_launch(void* const* d_in, const int* in_sizes, int n_in,
                              void* d_out, int out_size)
{
    const int B  = 2048;
    const int T  = in_sizes[0] / B;     // 1024
    const int TT = out_size / B;        // T + future = 1088

    const float* x    = (const float*)d_in[0];
    const float* Wih1 = (const float*)d_in[1];
    const float* Whh1 = (const float*)d_in[2];
    const float* bih1 = (const float*)d_in[3];
    const float* bhh1 = (const float*)d_in[4];
    const float* Wih2 = (const float*)d_in[5];
    const float* Whh2 = (const float*)d_in[6];
    const float* bih2 = (const float*)d_in[7];
    const float* bhh2 = (const float*)d_in[8];
    const float* Wlin = (const float*)d_in[9];
    const float* blin = (const float*)d_in[10];
    float* out = (float*)d_out;

    const int grid = (B + 2) / 3;       // 683 CTAs, 2 warps each
    lstm2_pipe_kernel<<<grid, 64>>>(x, Wih1, Whh1, bih1, bhh1,
                                    Wih2, Whh2, bih2, bhh2,
                                    Wlin, blin, out, B, T, TT);
}

// round 9
// speedup vs baseline: 1.4008x; 1.4008x over previous
#include <cuda_runtime.h>
#include <cstdint>

// 2-layer LSTM (HID=10), B=2048, T=1024, future=64.
// R8: dual-stream warps. Each warp carries TWO independent LSTM state sets
// (streams P and Q, 3 batch elements each => 6 elements/warp, grid=342).
// The two streams share weights (same lane -> same gate rows) and their
// instruction streams interleave, filling each other's dependency stalls.
// L2 weights (Wih2, Whh2) live in conflict-free per-lane shared memory to
// cut register pressure (~80 regs) so ptxas can pipeline both streams.
// tanh.approx nonlinearities (sigmoid = 0.5*tanh(z/2)+0.5, pre-folded).

#define HID 10

typedef unsigned long long u64;

__device__ __forceinline__ u64 pk(float a, float b) {
    u64 r; asm("mov.b64 %0, {%1, %2};" : "=l"(r) : "f"(a), "f"(b)); return r;
}
__device__ __forceinline__ float2 upk(u64 v) {
    float2 f; asm("mov.b64 {%0, %1}, %2;" : "=f"(f.x), "=f"(f.y) : "l"(v)); return f;
}
__device__ __forceinline__ u64 ffma2(u64 a, u64 b, u64 c) {
    u64 d; asm("fma.rn.f32x2 %0, %1, %2, %3;" : "=l"(d) : "l"(a), "l"(b), "l"(c)); return d;
}
__device__ __forceinline__ u64 fmul2(u64 a, u64 b) {
    u64 d; asm("mul.rn.f32x2 %0, %1, %2;" : "=l"(d) : "l"(a), "l"(b)); return d;
}
__device__ __forceinline__ u64 fadd2(u64 a, u64 b) {
    u64 d; asm("add.rn.f32x2 %0, %1, %2;" : "=l"(d) : "l"(a), "l"(b)); return d;
}
__device__ __forceinline__ float hsum(u64 v) { float2 f = upk(v); return f.x + f.y; }

__device__ __forceinline__ float tanh_fast(float z) {
    float r; asm("tanh.approx.f32 %0, %1;" : "=f"(r) : "f"(z)); return r;
}
// A is already z/2 : sigmoid(z) = 0.5*tanh(z/2) + 0.5
__device__ __forceinline__ float sig_half(float A) {
    return fmaf(tanh_fast(A), 0.5f, 0.5f);
}

// dot of 5 packed pairs + packed bias, tree-reduced
__device__ __forceinline__ u64 dot5(const u64* h, const u64* w, u64 biasp) {
    u64 a = ffma2(h[0], w[0], biasp);
    u64 b = fmul2(h[1], w[1]);
    a = ffma2(h[2], w[2], a);
    b = ffma2(h[3], w[3], b);
    a = ffma2(h[4], w[4], a);
    return fadd2(a, b);
}

// per-lane L2 weight stride in u64 (41 -> 328B; lane*82 words mod 32 banks,
// gcd(82,32)=2 => 16 distinct banks per 16-lane LDS.64 phase: conflict-free)
#define WSTRIDE 41

__global__ void __launch_bounds__(32, 8)
lstm2_dual_kernel(const float* __restrict__ x,
                  const float* __restrict__ Wih1, const float* __restrict__ Whh1,
                  const float* __restrict__ bih1, const float* __restrict__ bhh1,
                  const float* __restrict__ Wih2, const float* __restrict__ Whh2,
                  const float* __restrict__ bih2, const float* __restrict__ bhh2,
                  const float* __restrict__ Wlin, const float* __restrict__ blin,
                  float* __restrict__ out,
                  int B, int T, int TT)
{
    const int lane = threadIdx.x;
    int e = lane / HID;                 // element slot within warp: 0..2 (3 = idle)
    int u = lane - e * HID;
    const bool lane_ok = (e < 3);
    const int ec = lane_ok ? e : 2;
    const int g0 = ec * HID;

    // stream P -> elements base..base+2, stream Q -> base+3..base+5
    const int base = blockIdx.x * 6;
    const int bP = base + ec;
    const int bQ = base + 3 + ec;
    const bool wrP = lane_ok && (bP < B) && (u == 0);
    const bool wrQ = lane_ok && (bQ < B) && (u == 0);
    const int bcP = (bP < B) ? bP : (B - 1);
    const int bcQ = (bQ < B) ? bQ : (B - 1);

    const float scl[4] = {0.5f, 0.5f, 1.0f, 0.5f};   // i,f,o sigmoid-via-tanh; g plain
    const unsigned FULL = 0xffffffffu;

    // ---- L2 weights in per-lane shared memory ----
    // layout per lane: [0..19] Wih2 (4 gates x 5 pairs), [20..39] Whh2
    __shared__ u64 w2s[32 * WSTRIDE];
    u64* wl2 = &w2s[lane * WSTRIDE];

    // ---- register-resident weights (L1 + head) ----
    u64 Whh1r[4][5];
    float bias1[4], wx1[4];
    u64 b2p[4];
    u64 WL[5];
#pragma unroll
    for (int g = 0; g < 4; ++g) {
        const float s = scl[g];
        const int r = g * HID + u;
        bias1[g] = (__ldg(&bih1[r]) + __ldg(&bhh1[r])) * s;
        wx1[g]   = __ldg(&Wih1[r]) * s;
        b2p[g]   = pk((__ldg(&bih2[r]) + __ldg(&bhh2[r])) * s, 0.0f);
#pragma unroll
        for (int p = 0; p < 5; ++p) {
            float2 w;
            w = *(const float2*)&Whh1[r * HID + 2 * p]; Whh1r[g][p] = pk(w.x * s, w.y * s);
            w = *(const float2*)&Wih2[r * HID + 2 * p]; wl2[g * 5 + p]      = pk(w.x * s, w.y * s);
            w = *(const float2*)&Whh2[r * HID + 2 * p]; wl2[20 + g * 5 + p] = pk(w.x * s, w.y * s);
        }
    }
#pragma unroll
    for (int p = 0; p < 5; ++p) {
        float2 w = *(const float2*)&Wlin[2 * p];
        WL[p] = pk(w.x, w.y);
    }
    const float bl = __ldg(&blin[0]);
    __syncwarp();

    // ---- per-stream state ----
    u64 h1P[5], h2P[5], h1Q[5], h2Q[5];
#pragma unroll
    for (int p = 0; p < 5; ++p) { h1P[p] = 0ull; h2P[p] = 0ull; h1Q[p] = 0ull; h2Q[p] = 0ull; }
    float c1P = 0.0f, c2P = 0.0f, c1Q = 0.0f, c2Q = 0.0f;

    // one full LSTM step for one stream; returns y(t)
    auto step = [&](float xt, u64* h1p, u64* h2p, float& c1, float& c2) -> float {
        // L2, h2-dependent half (weights from smem; off the h1 critical path)
        u64 a2[4];
#pragma unroll
        for (int g = 0; g < 4; ++g)
            a2[g] = dot5(h2p, &wl2[20 + g * 5], b2p[g]);
        // layer 1
        float gt1[4];
#pragma unroll
        for (int g = 0; g < 4; ++g) {
            u64 biasx = pk(fmaf(wx1[g], xt, bias1[g]), 0.0f);
            gt1[g] = hsum(dot5(h1p, Whh1r[g], biasx));
        }
        const float si1 = sig_half(gt1[0]);
        const float sf1 = sig_half(gt1[1]);
        const float tg1 = tanh_fast(gt1[2]);
        const float so1 = sig_half(gt1[3]);
        c1 = fmaf(sf1, c1, si1 * tg1);
        const float h1u = so1 * tanh_fast(c1);
        {
            float v0 = __shfl_sync(FULL, h1u, g0 + 0);
            float v1 = __shfl_sync(FULL, h1u, g0 + 1);
            float v2 = __shfl_sync(FULL, h1u, g0 + 2);
            float v3 = __shfl_sync(FULL, h1u, g0 + 3);
            float v4 = __shfl_sync(FULL, h1u, g0 + 4);
            float v5 = __shfl_sync(FULL, h1u, g0 + 5);
            float v6 = __shfl_sync(FULL, h1u, g0 + 6);
            float v7 = __shfl_sync(FULL, h1u, g0 + 7);
            float v8 = __shfl_sync(FULL, h1u, g0 + 8);
            float v9 = __shfl_sync(FULL, h1u, g0 + 9);
            h1p[0] = pk(v0, v1); h1p[1] = pk(v2, v3); h1p[2] = pk(v4, v5);
            h1p[3] = pk(v6, v7); h1p[4] = pk(v8, v9);
        }
        // L2, h1-dependent half (weights from smem)
        float gt2[4];
#pragma unroll
        for (int g = 0; g < 4; ++g)
            gt2[g] = hsum(dot5(h1p, &wl2[g * 5], a2[g]));
        const float si2 = sig_half(gt2[0]);
        const float sf2 = sig_half(gt2[1]);
        const float tg2 = tanh_fast(gt2[2]);
        const float so2 = sig_half(gt2[3]);
        c2 = fmaf(sf2, c2, si2 * tg2);
        const float h2u = so2 * tanh_fast(c2);
        {
            float v0 = __shfl_sync(FULL, h2u, g0 + 0);
            float v1 = __shfl_sync(FULL, h2u, g0 + 1);
            float v2 = __shfl_sync(FULL, h2u, g0 + 2);
            float v3 = __shfl_sync(FULL, h2u, g0 + 3);
            float v4 = __shfl_sync(FULL, h2u, g0 + 4);
            float v5 = __shfl_sync(FULL, h2u, g0 + 5);
            float v6 = __shfl_sync(FULL, h2u, g0 + 6);
            float v7 = __shfl_sync(FULL, h2u, g0 + 7);
            float v8 = __shfl_sync(FULL, h2u, g0 + 8);
            float v9 = __shfl_sync(FULL, h2u, g0 + 9);
            h2p[0] = pk(v0, v1); h2p[1] = pk(v2, v3); h2p[2] = pk(v4, v5);
            h2p[3] = pk(v6, v7); h2p[4] = pk(v8, v9);
        }
        // y = h2 @ W_lin^T + b_lin
        u64 ya = ffma2(h2p[0], WL[0], pk(bl, 0.0f));
        u64 yb = fmul2(h2p[1], WL[1]);
        ya = ffma2(h2p[2], WL[2], ya);
        yb = ffma2(h2p[3], WL[3], yb);
        ya = ffma2(h2p[4], WL[4], ya);
        return hsum(fadd2(ya, yb));
    };

    const float* xrowP = x + (size_t)bcP * T;
    const float* xrowQ = x + (size_t)bcQ * T;
    float* orowP = out + (size_t)bcP * TT;
    float* orowQ = out + (size_t)bcQ * TT;

    float yP = 0.0f, yQ = 0.0f;
    int t = 0;

    // ---- main T loop: float4 x streams, prefetched one chunk (4 steps) ahead ----
    const bool fast4 = ((((uintptr_t)xrowP) & 15u) == 0) && ((((uintptr_t)xrowQ) & 15u) == 0)
                       && ((T & 3) == 0) && (T > 0);
    if (fast4) {
        const float4* xqP = (const float4*)xrowP;
        const float4* xqQ = (const float4*)xrowQ;
        const int nc = T >> 2;
        float4 xvP = __ldg(&xqP[0]);
        float4 xvQ = __ldg(&xqQ[0]);
        for (int ci = 0; ci < nc; ++ci) {
            float4 xnP = make_float4(0.f, 0.f, 0.f, 0.f);
            float4 xnQ = make_float4(0.f, 0.f, 0.f, 0.f);
            if (ci + 1 < nc) { xnP = __ldg(&xqP[ci + 1]); xnQ = __ldg(&xqQ[ci + 1]); }

            yP = step(xvP.x, h1P, h2P, c1P, c2P);
            yQ = step(xvQ.x, h1Q, h2Q, c1Q, c2Q);
            if (wrP) orowP[t + 0] = yP;
            if (wrQ) orowQ[t + 0] = yQ;

            yP = step(xvP.y, h1P, h2P, c1P, c2P);
            yQ = step(xvQ.y, h1Q, h2Q, c1Q, c2Q);
            if (wrP) orowP[t + 1] = yP;
            if (wrQ) orowQ[t + 1] = yQ;

            yP = step(xvP.z, h1P, h2P, c1P, c2P);
            yQ = step(xvQ.z, h1Q, h2Q, c1Q, c2Q);
            if (wrP) orowP[t + 2] = yP;
            if (wrQ) orowQ[t + 2] = yQ;

            yP = step(xvP.w, h1P, h2P, c1P, c2P);
            yQ = step(xvQ.w, h1Q, h2Q, c1Q, c2Q);
            if (wrP) orowP[t + 3] = yP;
            if (wrQ) orowQ[t + 3] = yQ;

            xvP = xnP; xvQ = xnQ; t += 4;
        }
    }
    // scalar tail (no-op for T=1024 aligned)
    for (; t < T; ++t) {
        yP = step(__ldg(&xrowP[t]), h1P, h2P, c1P, c2P);
        yQ = step(__ldg(&xrowQ[t]), h1Q, h2Q, c1Q, c2Q);
        if (wrP) orowP[t] = yP;
        if (wrQ) orowQ[t] = yQ;
    }
    // ---- future loop: x(t) = y(t-1) per stream ----
    for (; t < TT; ++t) {
        yP = step(yP, h1P, h2P, c1P, c2P);
        yQ = step(yQ, h1Q, h2Q, c1Q, c2Q);
        if (wrP) orowP[t] = yP;
        if (wrQ) orowQ[t] = yQ;
    }
}

extern "C" void kernel_launch(void* const* d_in, const int* in_sizes, int n_in,
                              void* d_out, int out_size)
{
    const int B  = 2048;
    const int T  = in_sizes[0] / B;     // 1024
    const int TT = out_size / B;        // T + future = 1088

    const float* x    = (const float*)d_in[0];
    const float* Wih1 = (const float*)d_in[1];
    const float* Whh1 = (const float*)d_in[2];
    const float* bih1 = (const float*)d_in[3];
    const float* bhh1 = (const float*)d_in[4];
    const float* Wih2 = (const float*)d_in[5];
    const float* Whh2 = (const float*)d_in[6];
    const float* bih2 = (const float*)d_in[7];
    const float* bhh2 = (const float*)d_in[8];
    const float* Wlin = (const float*)d_in[9];
    const float* blin = (const float*)d_in[10];
    float* out = (float*)d_out;

    const int grid = (B + 5) / 6;       // 342 warps, 6 elements each (2 streams x 3)
    lstm2_dual_kernel<<<grid, 32>>>(x, Wih1, Whh1, bih1, bhh1,
                                    Wih2, Whh2, bih2, bhh2,
                                    Wlin, blin, out, B, T, TT);
}